// round 11
// baseline (speedup 1.0000x reference)
#include <cuda_runtime.h>
#include <cstdint>

// Problem constants
#define KDIM   8192     // classes per row
#define MAXC   100
#define MINC   20
#define NTHREADS 256
// per-thread contiguous segment for the final ordered pass
#define EPT    (KDIM / NTHREADS)   // 32

// monotone float->uint key: order(key) == order(float)
__device__ __forceinline__ uint32_t f2key(float x) {
    uint32_t u = __float_as_uint(x);
    return (u & 0x80000000u) ? ~u : (u | 0x80000000u);
}

// padded smem index: insert 1 word per 32 -> conflict-free strided scalar access
__device__ __forceinline__ int padidx(int i) { return i + (i >> 5); }

// block-wide inclusive scan over 256 threads; wsum must be uint32[8] shared.
// After return, wsum[7] holds the block total.
__device__ __forceinline__ uint32_t blk_scan_incl(uint32_t v, volatile uint32_t* wsum) {
    const int lane = threadIdx.x & 31;
    const int w    = threadIdx.x >> 5;
#pragma unroll
    for (int d = 1; d < 32; d <<= 1) {
        uint32_t n = __shfl_up_sync(0xffffffffu, v, d);
        if (lane >= d) v += n;
    }
    if (lane == 31) wsum[w] = v;
    __syncthreads();
    if (threadIdx.x < 8) {
        uint32_t x = wsum[threadIdx.x];
#pragma unroll
        for (int d = 1; d < 8; d <<= 1) {
            uint32_t n = __shfl_up_sync(0xffu, x, d);
            if ((int)threadIdx.x >= d) x += n;
        }
        wsum[threadIdx.x] = x;
    }
    __syncthreads();
    if (w > 0) v += wsum[w - 1];
    return v;
}

// warp-aggregated shared histogram add (lowest participating lane is leader)
__device__ __forceinline__ void hist_add(int* hist, int bin, unsigned group_mask) {
    unsigned peers   = __match_any_sync(group_mask, bin);
    unsigned lanebit = 1u << (threadIdx.x & 31);
    if ((peers & (lanebit - 1)) == 0)          // lowest lane in peer group leads
        atomicAdd(&hist[bin], __popc(peers));
}

// Find bin b (descending order) such that count(bins > b) < r <= count(bins >= b).
// Writes {bin, count_strictly_above} into s_res. All threads must call.
// Invariant at every call site: 1 <= r <= sum(hist)  -> exactly one owner thread.
__device__ __forceinline__ void select_bin(int nbins, int r, const int* hist,
                                           volatile uint32_t* wsum, volatile int* s_res) {
    const int t  = threadIdx.x;
    const int CH = nbins >> 8;           // bins per thread (8 or 4)
    const int base = t * CH;
    int s = 0;
#pragma unroll 4
    for (int c = 0; c < CH; c++) s += hist[base + c];

    uint32_t incl  = blk_scan_incl((uint32_t)s, wsum);
    int total      = (int)wsum[7];
    int above      = total - (int)incl;  // count in chunks with index > t
    if (above < r && above + s >= r) {
        int cum = above;
        for (int b = base + CH - 1; b >= base; b--) {
            int h = hist[b];
            if (cum + h >= r) { s_res[0] = b; s_res[1] = cum; break; }
            cum += h;
        }
    }
    __syncthreads();
}

__global__ __launch_bounds__(NTHREADS, 1)
void retention_kernel(const float* __restrict__ logits,
                      float* __restrict__ bs_out,
                      float* __restrict__ cls_out,
                      float* __restrict__ msk_out) {
    __shared__ uint32_t s_keys[KDIM + KDIM / 32];   // 8448 words, padded layout
    __shared__ int      s_hist[2048];
    __shared__ uint32_t s_warp[8];
    __shared__ int      s_res[2];
    __shared__ int      s_cpos;

    const int t   = threadIdx.x;
    const int row = blockIdx.x;

    // init
    for (int c = t; c < 2048; c += NTHREADS) s_hist[c] = 0;
    if (t == 0) s_cpos = 0;
    __syncthreads();

    // ---- Pass 0: load row (float4, coalesced), convert to keys, cache in smem,
    //              count x>=0, and build round-1 histogram (top 11 bits) from regs.
    const float4* rp = reinterpret_cast<const float4*>(logits + (size_t)row * KDIM);
    int cpos = 0;
#pragma unroll
    for (int v = 0; v < 8; v++) {
        float4 f = rp[v * NTHREADS + t];
        uint32_t k0 = f2key(f.x), k1 = f2key(f.y), k2 = f2key(f.z), k3 = f2key(f.w);
        cpos += (k0 >= 0x80000000u) + (k1 >= 0x80000000u)
              + (k2 >= 0x80000000u) + (k3 >= 0x80000000u);
        int i0 = v * (NTHREADS * 4) + t * 4;
        int p0 = padidx(i0);                 // i0..i0+3 share the same pad offset
        s_keys[p0]     = k0;
        s_keys[p0 + 1] = k1;
        s_keys[p0 + 2] = k2;
        s_keys[p0 + 3] = k3;
        hist_add(s_hist, (int)(k0 >> 21), 0xffffffffu);
        hist_add(s_hist, (int)(k1 >> 21), 0xffffffffu);
        hist_add(s_hist, (int)(k2 >> 21), 0xffffffffu);
        hist_add(s_hist, (int)(k3 >> 21), 0xffffffffu);
    }
    atomicAdd(&s_cpos, cpos);
    __syncthreads();

    int nt = s_cpos;
    nt = min(max(nt, MINC), MAXC);
    int r = nt;

    // ---- Round 1 select (11 bits)
    select_bin(2048, r, s_hist, s_warp, s_res);
    const int b1 = s_res[0];
    r -= s_res[1];
    __syncthreads();

    // ---- Round 2 (next 11 bits), only keys whose top-11 == b1
    for (int c = t; c < 2048; c += NTHREADS) s_hist[c] = 0;
    __syncthreads();
    {
        const int pb = t * 33;    // padidx(t*32 + j) == t*33 + j for j<32
#pragma unroll 4
        for (int j = 0; j < EPT; j++) {
            uint32_t k = s_keys[pb + j];
            bool pred = ((int)(k >> 21) == b1);
            unsigned m = __ballot_sync(0xffffffffu, pred);
            if (pred) hist_add(s_hist, (int)((k >> 10) & 0x7FFu), m);
        }
    }
    __syncthreads();
    select_bin(2048, r, s_hist, s_warp, s_res);
    const int b2 = s_res[0];
    r -= s_res[1];
    __syncthreads();

    // ---- Round 3 (last 10 bits), only keys whose top-22 match
    for (int c = t; c < 1024; c += NTHREADS) s_hist[c] = 0;
    __syncthreads();
    {
        const uint32_t pref = ((uint32_t)b1 << 11) | (uint32_t)b2;
        const int pb = t * 33;
#pragma unroll 4
        for (int j = 0; j < EPT; j++) {
            uint32_t k = s_keys[pb + j];
            bool pred = ((k >> 10) == pref);
            unsigned m = __ballot_sync(0xffffffffu, pred);
            if (pred) hist_add(s_hist, (int)(k & 0x3FFu), m);
        }
    }
    __syncthreads();
    select_bin(1024, r, s_hist, s_warp, s_res);
    const int b3    = s_res[0];
    const int quota = r - s_res[1];   // pivot-equal elements to keep (lowest idx first)
    const uint32_t pivot = ((uint32_t)b1 << 21) | ((uint32_t)b2 << 10) | (uint32_t)b3;

    // ---- Final: each thread owns contiguous indices [t*32, t*32+32).
    // Included = (key > pivot) OR (key == pivot AND eq_rank < quota).
    // Scanning by ascending index emits cls indices already sorted ascending.
    int g = 0, e = 0;
    const int pb = t * 33;
#pragma unroll 4
    for (int j = 0; j < EPT; j++) {
        uint32_t k = s_keys[pb + j];
        g += (k > pivot);
        e += (k == pivot);
    }
    __syncthreads();
    uint32_t packed = ((uint32_t)g << 16) | (uint32_t)e;   // fields can't overflow (<=8192)
    uint32_t incl   = blk_scan_incl(packed, s_warp);
    uint32_t excl   = incl - packed;
    int gi = (int)(excl >> 16);
    int ei = (int)(excl & 0xFFFFu);

    // OUTPUTS ARE FLOAT32: -1 pads must be -1.0f, indices exact int->float.
    float* __restrict__ crow = cls_out + (size_t)row * MAXC;
#pragma unroll 4
    for (int j = 0; j < EPT; j++) {
        uint32_t k = s_keys[pb + j];
        int idx = t * EPT + j;
        if (k > pivot) {
            int pos = gi + min(ei, quota);
            crow[pos] = (float)idx;
            gi++;
        } else if (k == pivot) {
            if (ei < quota) crow[gi + ei] = (float)idx;
            ei++;
        }
    }

    if (t < MAXC) {
        bool valid = (t < nt);
        bs_out[(size_t)row * MAXC + t]  = valid ? (float)row : -1.0f;
        msk_out[(size_t)row * MAXC + t] = valid ? 1.0f : 0.0f;
        if (!valid) crow[t] = -1.0f;    // pad; positions < nt were scatter-written above
    }
}

extern "C" void kernel_launch(void* const* d_in, const int* in_sizes, int n_in,
                              void* d_out, int out_size) {
    const float* logits = (const float*)d_in[0];
    int rows = in_sizes[0] / KDIM;                   // 16384
    if (rows <= 0) return;
    float* out = (float*)d_out;
    float* bs  = out;
    float* cls = out + (size_t)rows * MAXC;
    float* msk = out + (size_t)2 * rows * MAXC;
    retention_kernel<<<rows, NTHREADS>>>(logits, bs, cls, msk);
}

// round 13
// speedup vs baseline: 1.4921x; 1.4921x over previous
#include <cuda_runtime.h>
#include <cstdint>

#define KDIM   8192
#define MAXC   100
#define MINC   20
#define NTHREADS 256
#define EPT    (KDIM / NTHREADS)   // 32
#define NBINS  1024                // top-10-bit histogram
#define CAP    512                 // candidate capacity (quick path)
#define CC     (CAP / NTHREADS)    // candidates per thread in emit scan (2)

// monotone float->uint key: order(key) == order(float)
__device__ __forceinline__ uint32_t f2key(float x) {
    uint32_t u = __float_as_uint(x);
    return (u & 0x80000000u) ? ~u : (u | 0x80000000u);
}

// padded smem index: 1 word per 32 -> conflict-free contiguous-per-thread sweeps
__device__ __forceinline__ int padidx(int i) { return i + (i >> 5); }

// block-wide inclusive scan over 256 threads; wsum = uint32[8] shared.
// After return, wsum[7] holds the block total. Caller must have a sync
// between a previous scan's reads and this scan's writes (all call sites do).
__device__ __forceinline__ uint32_t blk_scan_incl(uint32_t v, volatile uint32_t* wsum) {
    const int lane = threadIdx.x & 31;
    const int w    = threadIdx.x >> 5;
#pragma unroll
    for (int d = 1; d < 32; d <<= 1) {
        uint32_t n = __shfl_up_sync(0xffffffffu, v, d);
        if (lane >= d) v += n;
    }
    if (lane == 31) wsum[w] = v;
    __syncthreads();
    if (threadIdx.x < 8) {
        uint32_t x = wsum[threadIdx.x];
#pragma unroll
        for (int d = 1; d < 8; d <<= 1) {
            uint32_t n = __shfl_up_sync(0xffu, x, d);
            if ((int)threadIdx.x >= d) x += n;
        }
        wsum[threadIdx.x] = x;
    }
    __syncthreads();
    if (w > 0) v += wsum[w - 1];
    return v;
}

// warp-aggregated shared histogram add
__device__ __forceinline__ void hist_add(int* hist, int bin, unsigned group_mask) {
    unsigned peers   = __match_any_sync(group_mask, bin);
    unsigned lanebit = 1u << (threadIdx.x & 31);
    if ((peers & (lanebit - 1)) == 0)
        atomicAdd(&hist[bin], __popc(peers));
}

// Find bin b (descending) with count(bins > b) < r <= count(bins >= b).
// Writes {bin, count_strictly_above} into s_res. Invariant: 1 <= r <= sum.
__device__ __forceinline__ void select_bin(int r, const int* hist,
                                           volatile uint32_t* wsum, volatile int* s_res) {
    const int t    = threadIdx.x;
    const int CH   = NBINS >> 8;     // 4
    const int base = t * CH;
    int s = 0;
#pragma unroll
    for (int c = 0; c < CH; c++) s += hist[base + c];

    uint32_t incl = blk_scan_incl((uint32_t)s, wsum);
    int total     = (int)wsum[7];
    int above     = total - (int)incl;
    if (above < r && above + s >= r) {
        int cum = above;
        for (int b = base + CH - 1; b >= base; b--) {
            int h = hist[b];
            if (cum + h >= r) { s_res[0] = b; s_res[1] = cum; break; }
            cum += h;
        }
    }
    __syncthreads();
}

__global__ __launch_bounds__(NTHREADS, 1)
void retention_kernel(const float* __restrict__ logits,
                      float* __restrict__ bs_out,
                      float* __restrict__ cls_out,
                      float* __restrict__ msk_out) {
    __shared__ uint32_t s_keys[KDIM + KDIM / 32];   // 33 KB, padded
    __shared__ int      s_hist[NBINS];              // 4 KB
    __shared__ int      s_cand[CAP];                // 2 KB: candidate idx (+flag bit31)
    __shared__ uint32_t s_ckey[CAP];                // 2 KB: candidate keys
    __shared__ uint32_t s_warp[8];
    __shared__ int      s_res[2];
    __shared__ int      s_cpos;

    const int t    = threadIdx.x;
    const int row  = blockIdx.x;
    const int lane = t & 31;

    // init
#pragma unroll
    for (int c = 0; c < NBINS / NTHREADS; c++) s_hist[t + c * NTHREADS] = 0;
    if (t == 0) s_cpos = 0;
    __syncthreads();

    // ---- Pass 0: coalesced float4 load, keys -> smem, count x>=0,
    //              10-bit-top histogram from registers.
    const float4* rp = reinterpret_cast<const float4*>(logits + (size_t)row * KDIM);
    int cpos = 0;
#pragma unroll
    for (int v = 0; v < 8; v++) {
        float4 f = rp[v * NTHREADS + t];
        uint32_t k0 = f2key(f.x), k1 = f2key(f.y), k2 = f2key(f.z), k3 = f2key(f.w);
        cpos += (k0 >= 0x80000000u) + (k1 >= 0x80000000u)
              + (k2 >= 0x80000000u) + (k3 >= 0x80000000u);
        int p0 = padidx(v * (NTHREADS * 4) + t * 4);
        s_keys[p0]     = k0;
        s_keys[p0 + 1] = k1;
        s_keys[p0 + 2] = k2;
        s_keys[p0 + 3] = k3;
        hist_add(s_hist, (int)(k0 >> 22), 0xffffffffu);
        hist_add(s_hist, (int)(k1 >> 22), 0xffffffffu);
        hist_add(s_hist, (int)(k2 >> 22), 0xffffffffu);
        hist_add(s_hist, (int)(k3 >> 22), 0xffffffffu);
    }
    cpos = __reduce_add_sync(0xffffffffu, cpos);
    if (lane == 0) atomicAdd(&s_cpos, cpos);
    __syncthreads();

    int nt = min(max(s_cpos, MINC), MAXC);

    // ---- Round 1: which 10-bit bin holds the nt-th largest key
    select_bin(nt, s_hist, s_warp, s_res);
    const int b1 = s_res[0];
    const uint32_t cthr = (uint32_t)b1 << 22;   // candidate iff key >= cthr
    __syncthreads();

    // ---- Ordered compaction of candidates (index order preserved)
    const int pb = t * 33;                      // padidx(t*32 + j) = t*33 + j
    int cnt = 0;
#pragma unroll 8
    for (int j = 0; j < EPT; j++) cnt += (s_keys[pb + j] >= cthr);

    uint32_t incl = blk_scan_incl((uint32_t)cnt, s_warp);
    const int n_cand = (int)s_warp[7];
    int pos = (int)incl - cnt;

    float* __restrict__ crow = cls_out + (size_t)row * MAXC;

    if (n_cand <= CAP) {
        // ===== quick path (always taken for real data; n_cand ~ 30-60) =====
#pragma unroll 8
        for (int j = 0; j < EPT; j++) {
            uint32_t k = s_keys[pb + j];
            if (k >= cthr) { s_cand[pos] = t * EPT + j; s_ckey[pos] = k; pos++; }
        }
        __syncthreads();

        // exact rank among candidates; ties -> lowest storage order (= lowest idx)
        for (int i = t; i < n_cand; i += NTHREADS) {
            uint32_t ki = s_ckey[i];
            int rank = 0;
            for (int j2 = 0; j2 < n_cand; j2++) {     // broadcast smem reads
                uint32_t kj = s_ckey[j2];
                rank += (kj > ki) || (kj == ki && j2 < i);
            }
            if (rank < nt) s_cand[i] |= (int)0x80000000;  // include flag
        }
        __syncthreads();

        // index-ordered emit: scan include flags over storage order
        int f = 0;
#pragma unroll
        for (int c = 0; c < CC; c++) {
            int i = t * CC + c;
            if (i < n_cand) f += (s_cand[i] < 0);
        }
        incl = blk_scan_incl((uint32_t)f, s_warp);
        int p2 = (int)incl - f;
#pragma unroll
        for (int c = 0; c < CC; c++) {
            int i = t * CC + c;
            if (i < n_cand) {
                int v = s_cand[i];
                if (v < 0) { crow[p2] = (float)(v & 0x7FFFFFFF); p2++; }
            }
        }
    } else {
        // ===== cold fallback: exact pivot via bitwise binary search =====
        __syncthreads();
        uint32_t pv = cthr;                      // count(>= pv) = n_cand >= nt
        for (int bit = 21; bit >= 0; bit--) {
            uint32_t cv = pv | (1u << bit);
            if (t == 0) s_cpos = 0;
            __syncthreads();
            int c2 = 0;
#pragma unroll 8
            for (int j = 0; j < EPT; j++) c2 += (s_keys[pb + j] >= cv);
            c2 = __reduce_add_sync(0xffffffffu, c2);
            if (lane == 0) atomicAdd(&s_cpos, c2);
            __syncthreads();
            if (s_cpos >= nt) pv = cv;
            __syncthreads();
        }
        // g/e emit with exact pivot pv
        int g = 0, e = 0;
#pragma unroll 8
        for (int j = 0; j < EPT; j++) {
            uint32_t k = s_keys[pb + j];
            g += (k > pv);
            e += (k == pv);
        }
        uint32_t packed = ((uint32_t)g << 16) | (uint32_t)e;
        incl = blk_scan_incl(packed, s_warp);
        uint32_t tot  = s_warp[7];
        int quota     = nt - (int)(tot >> 16);
        uint32_t excl = incl - packed;
        int gi = (int)(excl >> 16);
        int ei = (int)(excl & 0xFFFFu);
#pragma unroll 4
        for (int j = 0; j < EPT; j++) {
            uint32_t k = s_keys[pb + j];
            int idx = t * EPT + j;
            if (k > pv) {
                crow[gi + min(ei, quota)] = (float)idx;
                gi++;
            } else if (k == pv) {
                if (ei < quota) crow[gi + ei] = (float)idx;
                ei++;
            }
        }
    }

    // pads + aux outputs (float32; -1.0f padding)
    if (t < MAXC) {
        bool valid = (t < nt);
        bs_out[(size_t)row * MAXC + t]  = valid ? (float)row : -1.0f;
        msk_out[(size_t)row * MAXC + t] = valid ? 1.0f : 0.0f;
        if (!valid) crow[t] = -1.0f;
    }
}

extern "C" void kernel_launch(void* const* d_in, const int* in_sizes, int n_in,
                              void* d_out, int out_size) {
    const float* logits = (const float*)d_in[0];
    int rows = in_sizes[0] / KDIM;
    if (rows <= 0) return;
    float* out = (float*)d_out;
    float* bs  = out;
    float* cls = out + (size_t)rows * MAXC;
    float* msk = out + (size_t)2 * rows * MAXC;
    retention_kernel<<<rows, NTHREADS>>>(logits, bs, cls, msk);
}

// round 14
// speedup vs baseline: 1.8271x; 1.2245x over previous
#include <cuda_runtime.h>
#include <cstdint>

#define KDIM   8192
#define MAXC   100
#define MINC   20
#define NTHREADS 256
#define EPT    (KDIM / NTHREADS)   // 32
#define CAP    1024                // candidate capacity

#define THR1   (-1.0f)             // primary candidate threshold (~51 hits/row)
#define THR2   (-3.0f)             // secondary (~547 hits/row), rare
#define FULL   0xffffffffu

// monotone float->uint key: order(key) == order(float)
__device__ __forceinline__ uint32_t f2key(float x) {
    uint32_t u = __float_as_uint(x);
    return (u & 0x80000000u) ? ~u : (u | 0x80000000u);
}

// block-wide inclusive scan over 256 threads (used only in cold fallback)
__device__ __forceinline__ uint32_t blk_scan_incl(uint32_t v, volatile uint32_t* wsum) {
    const int lane = threadIdx.x & 31;
    const int w    = threadIdx.x >> 5;
#pragma unroll
    for (int d = 1; d < 32; d <<= 1) {
        uint32_t n = __shfl_up_sync(FULL, v, d);
        if (lane >= d) v += n;
    }
    if (lane == 31) wsum[w] = v;
    __syncthreads();
    if (threadIdx.x < 8) {
        uint32_t x = wsum[threadIdx.x];
#pragma unroll
        for (int d = 1; d < 8; d <<= 1) {
            uint32_t n = __shfl_up_sync(0xffu, x, d);
            if ((int)threadIdx.x >= d) x += n;
        }
        wsum[threadIdx.x] = x;
    }
    __syncthreads();
    if (w > 0) v += wsum[w - 1];
    return v;
}

// ballot-aggregated candidate push: one shared atomic per warp per component
__device__ __forceinline__ void push_cand(bool c, float f, int idx,
                                          int* s_n, uint32_t* s_ckey, int* s_cand) {
    unsigned m = __ballot_sync(FULL, c);
    if (m) {                                   // warp-uniform branch
        int lane   = threadIdx.x & 31;
        int leader = __ffs(m) - 1;
        int base   = 0;
        if (lane == leader) base = atomicAdd(s_n, __popc(m));
        base = __shfl_sync(FULL, base, leader);
        if (c) {
            int p = base + __popc(m & ((1u << lane) - 1u));
            if (p < CAP) { s_ckey[p] = f2key(f); s_cand[p] = idx; }
        }
    }
}

__global__ __launch_bounds__(NTHREADS, 6)
void retention_kernel(const float* __restrict__ logits,
                      float* __restrict__ bs_out,
                      float* __restrict__ cls_out,
                      float* __restrict__ msk_out) {
    __shared__ uint32_t s_ckey[CAP];    // candidate keys
    __shared__ int      s_cand[CAP];    // candidate indices
    __shared__ int      s_flag[CAP];    // include flags
    __shared__ uint32_t s_warp[8];
    __shared__ int      s_c0, s_n, s_tot;

    const int t    = threadIdx.x;
    const int row  = blockIdx.x;
    const int lane = t & 31;

    if (t == 0) { s_c0 = 0; s_n = 0; }
    __syncthreads();

    // ---- Single streaming pass: count(x>=0) + gather candidates (x >= THR1).
    const float4* rp = reinterpret_cast<const float4*>(logits + (size_t)row * KDIM);
    int c0 = 0;
#pragma unroll
    for (int v = 0; v < 8; v++) {
        float4 f = rp[v * NTHREADS + t];
        c0 += (f.x >= 0.0f) + (f.y >= 0.0f) + (f.z >= 0.0f) + (f.w >= 0.0f);
        int idx0 = (v * NTHREADS + t) * 4;
        push_cand(f.x >= THR1, f.x, idx0 + 0, &s_n, s_ckey, s_cand);
        push_cand(f.y >= THR1, f.y, idx0 + 1, &s_n, s_ckey, s_cand);
        push_cand(f.z >= THR1, f.z, idx0 + 2, &s_n, s_ckey, s_cand);
        push_cand(f.w >= THR1, f.w, idx0 + 3, &s_n, s_ckey, s_cand);
    }
    c0 = __reduce_add_sync(FULL, c0);
    if (lane == 0) atomicAdd(&s_c0, c0);
    __syncthreads();

    const int nt = min(max(s_c0, MINC), MAXC);
    int n = s_n;

    float* __restrict__ crow = cls_out + (size_t)row * MAXC;
    bool done = false;

    // ---- secondary gather if too few candidates (rare; block-uniform branch)
    if (n < nt) {
        __syncthreads();
        if (t == 0) s_n = 0;
        __syncthreads();
#pragma unroll
        for (int v = 0; v < 8; v++) {
            float4 f = rp[v * NTHREADS + t];
            int idx0 = (v * NTHREADS + t) * 4;
            push_cand(f.x >= THR2, f.x, idx0 + 0, &s_n, s_ckey, s_cand);
            push_cand(f.y >= THR2, f.y, idx0 + 1, &s_n, s_ckey, s_cand);
            push_cand(f.z >= THR2, f.z, idx0 + 2, &s_n, s_ckey, s_cand);
            push_cand(f.w >= THR2, f.w, idx0 + 3, &s_n, s_ckey, s_cand);
        }
        __syncthreads();
        n = s_n;
    }

    if (n >= nt && n <= CAP) {
        // ===== quick path: exact selection among n candidates (n ~ 51) =====
        // pass 1: inclusion by exact descending rank; ties -> lowest index.
        for (int i = t; i < n; i += NTHREADS) {
            uint32_t ki = s_ckey[i];
            int idxi    = s_cand[i];
            int rank = 0;
            for (int j = 0; j < n; j++) {           // broadcast smem reads
                uint32_t kj = s_ckey[j];
                rank += (kj > ki) || (kj == ki && s_cand[j] < idxi);
            }
            s_flag[i] = (rank < nt);
        }
        __syncthreads();
        // pass 2: output position = #included with smaller index (ascending emit)
        for (int i = t; i < n; i += NTHREADS) {
            if (s_flag[i]) {
                int idxi = s_cand[i];
                int pos = 0;
                for (int j = 0; j < n; j++)
                    pos += s_flag[j] && (s_cand[j] < idxi);
                crow[pos] = (float)idxi;
            }
        }
        done = true;
    }

    if (!done) {
        // ===== cold exact fallback: 32-bit binary-search pivot over gmem =====
        uint32_t pv = 0;
        for (int bit = 31; bit >= 0; bit--) {
            uint32_t cv = pv | (1u << bit);
            if (t == 0) s_tot = 0;
            __syncthreads();
            int c = 0;
#pragma unroll
            for (int v = 0; v < 8; v++) {
                float4 f = rp[v * NTHREADS + t];
                c += (f2key(f.x) >= cv) + (f2key(f.y) >= cv)
                   + (f2key(f.z) >= cv) + (f2key(f.w) >= cv);
            }
            c = __reduce_add_sync(FULL, c);
            if (lane == 0) atomicAdd(&s_tot, c);
            __syncthreads();
            if (s_tot >= nt) pv = cv;
            __syncthreads();
        }
        // ordered g/e emit; thread t owns contiguous elements [t*EPT, t*EPT+EPT)
        const float* rowp = logits + (size_t)row * KDIM;
        int g = 0, e = 0;
#pragma unroll 4
        for (int j = 0; j < EPT; j++) {
            uint32_t k = f2key(rowp[t * EPT + j]);
            g += (k > pv);
            e += (k == pv);
        }
        uint32_t packed = ((uint32_t)g << 16) | (uint32_t)e;
        uint32_t incl   = blk_scan_incl(packed, s_warp);
        uint32_t tot    = s_warp[7];
        int quota       = nt - (int)(tot >> 16);
        uint32_t excl   = incl - packed;
        int gi = (int)(excl >> 16);
        int ei = (int)(excl & 0xFFFFu);
#pragma unroll 4
        for (int j = 0; j < EPT; j++) {
            uint32_t k = f2key(rowp[t * EPT + j]);
            int idx = t * EPT + j;
            if (k > pv) {
                crow[gi + min(ei, quota)] = (float)idx;
                gi++;
            } else if (k == pv) {
                if (ei < quota) crow[gi + ei] = (float)idx;
                ei++;
            }
        }
    }

    // pads + aux outputs (float32; -1.0f padding). Disjoint from emit writes.
    if (t < MAXC) {
        bool valid = (t < nt);
        bs_out[(size_t)row * MAXC + t]  = valid ? (float)row : -1.0f;
        msk_out[(size_t)row * MAXC + t] = valid ? 1.0f : 0.0f;
        if (!valid) crow[t] = -1.0f;
    }
}

extern "C" void kernel_launch(void* const* d_in, const int* in_sizes, int n_in,
                              void* d_out, int out_size) {
    const float* logits = (const float*)d_in[0];
    int rows = in_sizes[0] / KDIM;
    if (rows <= 0) return;
    float* out = (float*)d_out;
    float* bs  = out;
    float* cls = out + (size_t)rows * MAXC;
    float* msk = out + (size_t)2 * rows * MAXC;
    retention_kernel<<<rows, NTHREADS>>>(logits, bs, cls, msk);
}

// round 16
// speedup vs baseline: 2.3692x; 1.2967x over previous
#include <cuda_runtime.h>
#include <cstdint>

#define KDIM   8192
#define MAXC   100
#define MINC   20
#define NTHREADS 256
#define EPT    (KDIM / NTHREADS)   // 32
#define CAP    1024
#define CPT    (CAP / NTHREADS)    // 4 candidates per thread in quick path
#define THR1   (-1.0f)             // ~51 hits/row on this data
#define THR2   (-3.0f)             // ~547 hits/row (secondary, rare)
#define FULL   0xffffffffu
#define KEY_ZERO 0x7FFFFFFFu       // key(-0.0); key >= KEY_ZERO  <=>  x >= 0

// monotone float->uint key: order(key) == order(float)
__device__ __forceinline__ uint32_t f2key(float x) {
    uint32_t u = __float_as_uint(x);
    return (u & 0x80000000u) ? ~u : (u | 0x80000000u);
}

// block-wide inclusive scan (cold fallback only)
__device__ __forceinline__ uint32_t blk_scan_incl(uint32_t v, volatile uint32_t* wsum) {
    const int lane = threadIdx.x & 31;
    const int w    = threadIdx.x >> 5;
#pragma unroll
    for (int d = 1; d < 32; d <<= 1) {
        uint32_t n = __shfl_up_sync(FULL, v, d);
        if (lane >= d) v += n;
    }
    if (lane == 31) wsum[w] = v;
    __syncthreads();
    if (threadIdx.x < 8) {
        uint32_t x = wsum[threadIdx.x];
#pragma unroll
        for (int d = 1; d < 8; d <<= 1) {
            uint32_t n = __shfl_up_sync(0xffu, x, d);
            if ((int)threadIdx.x >= d) x += n;
        }
        wsum[threadIdx.x] = x;
    }
    __syncthreads();
    if (w > 0) v += wsum[w - 1];
    return v;
}

__global__ __launch_bounds__(NTHREADS, 8)
void retention_kernel(const float* __restrict__ logits,
                      float* __restrict__ bs_out,
                      float* __restrict__ cls_out,
                      float* __restrict__ msk_out) {
    __shared__ uint32_t s_ckey[CAP];    // candidate keys
    __shared__ int      s_cand[CAP];    // candidate indices (bit31 = include flag)
    __shared__ uint32_t s_warp[8];
    __shared__ int      s_n, s_c0, s_tot;

    const int t    = threadIdx.x;
    const int row  = blockIdx.x;
    const int lane = t & 31;

    if (t == 0) { s_n = 0; s_c0 = 0; }
    __syncthreads();

    // ---- Hot pass: 1 FSETP + rare branch per element. No per-element count.
    const float4* rp = reinterpret_cast<const float4*>(logits + (size_t)row * KDIM);
#pragma unroll
    for (int v = 0; v < 8; v++) {
        float4 f = rp[v * NTHREADS + t];
        int idx0 = (v * NTHREADS + t) * 4;
        if (f.x >= THR1) { int p = atomicAdd(&s_n, 1); if (p < CAP) { s_ckey[p] = f2key(f.x); s_cand[p] = idx0;     } }
        if (f.y >= THR1) { int p = atomicAdd(&s_n, 1); if (p < CAP) { s_ckey[p] = f2key(f.y); s_cand[p] = idx0 + 1; } }
        if (f.z >= THR1) { int p = atomicAdd(&s_n, 1); if (p < CAP) { s_ckey[p] = f2key(f.z); s_cand[p] = idx0 + 2; } }
        if (f.w >= THR1) { int p = atomicAdd(&s_n, 1); if (p < CAP) { s_ckey[p] = f2key(f.w); s_cand[p] = idx0 + 3; } }
    }
    __syncthreads();
    int n = s_n;

    // ---- c0 = count(x >= 0), derived from candidates (valid iff n <= CAP,
    //      since {x>=0} subset of {x>=THR1}).
    if (n <= CAP) {
        int c = 0;
        for (int i = t; i < n; i += NTHREADS) c += (s_ckey[i] >= KEY_ZERO);
        c = __reduce_add_sync(FULL, c);
        if (lane == 0 && c) atomicAdd(&s_c0, c);
    }
    __syncthreads();

    int  nt   = min(max(s_c0, MINC), MAXC);   // valid only when n <= CAP
    bool have = (n <= CAP);

    // ---- secondary gather (rare, block-uniform): enough-candidates guarantee
    if (have && n < nt) {           // c0 valid here, nt = 20 > n
        if (t == 0) s_n = 0;
        __syncthreads();
#pragma unroll
        for (int v = 0; v < 8; v++) {
            float4 f = rp[v * NTHREADS + t];    // row is hot in L2
            int idx0 = (v * NTHREADS + t) * 4;
            if (f.x >= THR2) { int p = atomicAdd(&s_n, 1); if (p < CAP) { s_ckey[p] = f2key(f.x); s_cand[p] = idx0;     } }
            if (f.y >= THR2) { int p = atomicAdd(&s_n, 1); if (p < CAP) { s_ckey[p] = f2key(f.y); s_cand[p] = idx0 + 1; } }
            if (f.z >= THR2) { int p = atomicAdd(&s_n, 1); if (p < CAP) { s_ckey[p] = f2key(f.z); s_cand[p] = idx0 + 2; } }
            if (f.w >= THR2) { int p = atomicAdd(&s_n, 1); if (p < CAP) { s_ckey[p] = f2key(f.w); s_cand[p] = idx0 + 3; } }
        }
        __syncthreads();
        n = s_n;
    }
    have = have && (n >= nt) && (n <= CAP);

    float* __restrict__ crow = cls_out + (size_t)row * MAXC;

    if (have) {
        // ===== quick path: exact top-nt among n candidates (n ~ 51) =====
        // pass 1: exact descending rank; ties -> lowest index. Deferred flag
        // writes (regs) so concurrent readers see clean s_cand values.
        int incv[CPT];
#pragma unroll
        for (int c = 0; c < CPT; c++) {
            int i = t + c * NTHREADS;
            incv[c] = 0;
            if (i < n) {
                uint32_t ki = s_ckey[i];
                int idxi    = s_cand[i];
                int rank = 0;
                for (int j = 0; j < n; j++) {        // broadcast smem reads
                    uint32_t kj = s_ckey[j];
                    rank += (kj > ki) || (kj == ki && s_cand[j] < idxi);
                }
                incv[c] = (rank < nt);
            }
        }
        __syncthreads();
#pragma unroll
        for (int c = 0; c < CPT; c++) {
            int i = t + c * NTHREADS;
            if (i < n && incv[c]) s_cand[i] |= (int)0x80000000;
        }
        __syncthreads();
        // pass 2: output slot = #included with smaller class index
#pragma unroll
        for (int c = 0; c < CPT; c++) {
            int i = t + c * NTHREADS;
            if (i < n && incv[c]) {
                int idxi = s_cand[i] & 0x7FFFFFFF;
                int pos = 0;
                for (int j = 0; j < n; j++) {
                    int w = s_cand[j];
                    pos += (w < 0) && ((w & 0x7FFFFFFF) < idxi);
                }
                crow[pos] = (float)idxi;
            }
        }
    } else {
        // ===== cold exact fallback: recompute c0, binary-search pivot =====
        if (t == 0) s_tot = 0;
        __syncthreads();
        {
            int c = 0;
#pragma unroll
            for (int v = 0; v < 8; v++) {
                float4 f = rp[v * NTHREADS + t];
                c += (f.x >= 0.0f) + (f.y >= 0.0f) + (f.z >= 0.0f) + (f.w >= 0.0f);
            }
            c = __reduce_add_sync(FULL, c);
            if (lane == 0) atomicAdd(&s_tot, c);
        }
        __syncthreads();
        nt = min(max(s_tot, MINC), MAXC);

        uint32_t pv = 0;
        for (int bit = 31; bit >= 0; bit--) {
            uint32_t cv = pv | (1u << bit);
            if (t == 0) s_tot = 0;
            __syncthreads();
            int c = 0;
#pragma unroll
            for (int v = 0; v < 8; v++) {
                float4 f = rp[v * NTHREADS + t];
                c += (f2key(f.x) >= cv) + (f2key(f.y) >= cv)
                   + (f2key(f.z) >= cv) + (f2key(f.w) >= cv);
            }
            c = __reduce_add_sync(FULL, c);
            if (lane == 0) atomicAdd(&s_tot, c);
            __syncthreads();
            if (s_tot >= nt) pv = cv;
            __syncthreads();
        }
        // ordered g/e emit; thread t owns contiguous [t*EPT, t*EPT+EPT)
        const float* rowp = logits + (size_t)row * KDIM;
        int g = 0, e = 0;
#pragma unroll 4
        for (int j = 0; j < EPT; j++) {
            uint32_t k = f2key(rowp[t * EPT + j]);
            g += (k > pv);
            e += (k == pv);
        }
        uint32_t packed = ((uint32_t)g << 16) | (uint32_t)e;
        uint32_t incl   = blk_scan_incl(packed, s_warp);
        uint32_t tot    = s_warp[7];
        int quota       = nt - (int)(tot >> 16);
        uint32_t excl   = incl - packed;
        int gi = (int)(excl >> 16);
        int ei = (int)(excl & 0xFFFFu);
#pragma unroll 4
        for (int j = 0; j < EPT; j++) {
            uint32_t k = f2key(rowp[t * EPT + j]);
            int idx = t * EPT + j;
            if (k > pv) {
                crow[gi + min(ei, quota)] = (float)idx;
                gi++;
            } else if (k == pv) {
                if (ei < quota) crow[gi + ei] = (float)idx;
                ei++;
            }
        }
    }

    // pads + aux outputs (float32; -1.0f padding). Disjoint positions.
    if (t < MAXC) {
        bool valid = (t < nt);
        bs_out[(size_t)row * MAXC + t]  = valid ? (float)row : -1.0f;
        msk_out[(size_t)row * MAXC + t] = valid ? 1.0f : 0.0f;
        if (!valid) crow[t] = -1.0f;
    }
}

extern "C" void kernel_launch(void* const* d_in, const int* in_sizes, int n_in,
                              void* d_out, int out_size) {
    const float* logits = (const float*)d_in[0];
    int rows = in_sizes[0] / KDIM;
    if (rows <= 0) return;
    float* out = (float*)d_out;
    float* bs  = out;
    float* cls = out + (size_t)rows * MAXC;
    float* msk = out + (size_t)2 * rows * MAXC;
    retention_kernel<<<rows, NTHREADS>>>(logits, bs, cls, msk);
}